// round 6
// baseline (speedup 1.0000x reference)
#include <cuda_runtime.h>

// out[b, f, s] = x[b, 0, s] * w[f, s] + b[f, s]
// B=128, F=256, S=4096. HBM-write-bound: 512 MiB out.
//
// R6: persistent grid of 296 CTAs (2/SM on 148 SMs), static partition of
// 16384 work items. Item = (s-chunk sc, filter-group fg, batch b); items with
// the same (sc,fg) are consecutive, so the 8 cached w/bias chunks reload at
// most twice per CTA. Removes wave quantization (was 3.46 waves, 0.46 tail).

#define S4      1024        // float4 per row (4096 floats)
#define NFILT   256
#define BATCH   128
#define FT      8           // filters per item (register-cached w/bias)
#define NCTA    296         // 2 CTAs per SM x 148 SMs
#define NITEMS  16384       // 4 s-chunks * 32 filter groups * 128 batches

__global__ __launch_bounds__(256, 2) void dense_filter_expand_kernel(
    const float4* __restrict__ x,     // [B, S4]
    const float4* __restrict__ w,     // [F, S4]
    const float4* __restrict__ bias,  // [F, S4]
    float4* __restrict__ out)         // [B, F, S4]
{
    const int t = threadIdx.x;                 // 0..255
    const int c = blockIdx.x;                  // 0..295

    // Static partition: first `rem` CTAs get nb+1 items.
    const int nb    = NITEMS / NCTA;           // 55
    const int rem   = NITEMS % NCTA;           // 104
    const int start = c * nb + (c < rem ? c : rem);
    const int cnt   = nb + (c < rem ? 1 : 0);

    int gprev = -1;
    int s4 = 0, f0 = 0;
    float4 wv[FT], bv[FT];

#pragma unroll 1
    for (int k = 0; k < cnt; k++) {
        const int i = start + k;
        const int g = i >> 7;                  // (sc, fg) group: 0..127
        const int b = i & 127;                 // batch

        if (g != gprev) {                      // at most twice per CTA
            const int sc = g & 3;
            const int fg = g >> 2;
            s4 = sc * 256 + t;
            f0 = fg * FT;
#pragma unroll
            for (int ff = 0; ff < FT; ff++) {
                wv[ff] = __ldg(&w[(size_t)(f0 + ff) * S4 + s4]);
                bv[ff] = __ldg(&bias[(size_t)(f0 + ff) * S4 + s4]);
            }
            gprev = g;
        }

        const float4 xv = __ldg(&x[(size_t)b * S4 + s4]);
        float4* obase = out + ((size_t)b * NFILT + f0) * S4 + s4;

#pragma unroll
        for (int ff = 0; ff < FT; ff++) {
            float4 o;
            o.x = fmaf(xv.x, wv[ff].x, bv[ff].x);
            o.y = fmaf(xv.y, wv[ff].y, bv[ff].y);
            o.z = fmaf(xv.z, wv[ff].z, bv[ff].z);
            o.w = fmaf(xv.w, wv[ff].w, bv[ff].w);
            // Streaming store: output is write-once, never re-read.
            __stcs(obase + (size_t)ff * S4, o);
        }
    }
}

extern "C" void kernel_launch(void* const* d_in, const int* in_sizes, int n_in,
                              void* d_out, int out_size) {
    const float4* x    = (const float4*)d_in[0];   // inputs [128,1,4096]
    const float4* w    = (const float4*)d_in[1];   // w [256,4096]
    const float4* bias = (const float4*)d_in[2];   // b [256,4096]
    float4* out = (float4*)d_out;

    dense_filter_expand_kernel<<<NCTA, 256>>>(x, w, bias, out);
}